// round 6
// baseline (speedup 1.0000x reference)
#include <cuda_runtime.h>
#include <math.h>

// Problem constants (fixed by the reference)
#define BATCH 8192
#define NCLS  1000
#define DDIM  4096

#define TILE_D      1024
#define NT_D        (DDIM / TILE_D)       // 4 tiles over D
#define NF_BLOCKS   (NCLS * NT_D)         // 4000 fused blocks
#define CE_BLOCKS   (BATCH / 4)           // 2048 CE blocks (warp-per-row, 4/block)
#define FIRST_CE    1
#define FIRST_FUSED (FIRST_CE + CE_BLOCKS)
#define GRID        (FIRST_FUSED + NF_BLOCKS)
#define MEGA_T      128
#define NSLOTS      64

// ---------------------------------------------------------------------------
// Device scratch (no allocations allowed)
// ---------------------------------------------------------------------------
__device__ int    g_offsets[1025];     // exclusive class offsets (bins padded to 1024)
__device__ int    g_rows[BATCH];       // row ids grouped by class
__device__ int    g_rank[BATCH];       // per-row rank within its class
__device__ double g_l1_slots[NSLOTS];
__device__ double g_l2_slots[NSLOTS];
__device__ int    g_flag = 0;          // prep-done flag (reset by finalize)

// ---------------------------------------------------------------------------
// Element op: one EX2 serves sigmoid and BCE.
//   e = exp(-|x|); r = 1/(1+e); sig = x>=0 ? r : 1-r
//   bce += max(x,0) - x*y + log(1+e)
// ---------------------------------------------------------------------------
__device__ __forceinline__ void elem_op(float x, float y, float& acc, float& bce) {
    const float e = __expf(-fabsf(x));
    const float r = 1.f / (1.f + e);
    acc += (x >= 0.f) ? r : (1.f - r);
    bce += fmaxf(x, 0.f) - x * y + __logf(1.f + e);
}

__device__ __forceinline__ void acc4(const float4 x4, const float4 y4,
                                     float4& acc, float& bce) {
    elem_op(x4.x, y4.x, acc.x, bce);
    elem_op(x4.y, y4.y, acc.y, bce);
    elem_op(x4.z, y4.z, acc.z, bce);
    elem_op(x4.w, y4.w, acc.w, bce);
}

// ---------------------------------------------------------------------------
// mega kernel:
//   bid == 0                 -> prep (hist/rank + scan + scatter), sets g_flag
//   1 <= bid < FIRST_FUSED   -> CE (warp-per-row, 4 rows/block) [indep of prep]
//   bid >= FIRST_FUSED       -> fused segment-sum+BCE tile (spins on g_flag)
// ---------------------------------------------------------------------------
__global__ __launch_bounds__(MEGA_T)
void mega_kernel(const float* __restrict__ dense_out,
                 const float* __restrict__ dense_labels,
                 const float* __restrict__ logits,
                 const int*   __restrict__ target,
                 float* __restrict__ out_sum,
                 float* __restrict__ total_out) {
    const int bid = blockIdx.x;
    const int tid = threadIdx.x;
    __shared__ float sred[MEGA_T / 32];

    if (bid == 0) {
        // =================== prep role (single block, 128 threads) ==========
        __shared__ int scnt[1024];   // per-class counts
        __shared__ int soff[1024];   // per-class exclusive offsets
        __shared__ int swarp[4];

        if (tid < NSLOTS) { g_l1_slots[tid] = 0.0; g_l2_slots[tid] = 0.0; }
        #pragma unroll
        for (int i = tid; i < 1024; i += MEGA_T) scnt[i] = 0;
        __syncthreads();

        // pass 1: histogram; atomic return value IS the row's rank
        const int4* t4 = reinterpret_cast<const int4*>(target);
        #pragma unroll
        for (int i = tid; i < BATCH / 4; i += MEGA_T) {
            int4 t = t4[i];
            int b = i * 4;
            g_rank[b]     = atomicAdd(&scnt[t.x], 1);
            g_rank[b + 1] = atomicAdd(&scnt[t.y], 1);
            g_rank[b + 2] = atomicAdd(&scnt[t.z], 1);
            g_rank[b + 3] = atomicAdd(&scnt[t.w], 1);
        }
        __syncthreads();

        // totals for the output
        for (int j = tid; j < NCLS; j += MEGA_T) total_out[j] = (float)scnt[j];

        // scan: thread t owns bins [8t, 8t+8)
        int c[8], s = 0;
        #pragma unroll
        for (int k = 0; k < 8; k++) { c[k] = scnt[tid * 8 + k]; s += c[k]; }
        const int lane = tid & 31, wid = tid >> 5;
        int incl = s;
        #pragma unroll
        for (int o = 1; o < 32; o <<= 1) {
            int n = __shfl_up_sync(0xffffffffu, incl, o);
            if (lane >= o) incl += n;
        }
        if (lane == 31) swarp[wid] = incl;
        __syncthreads();
        int wbase = 0;
        #pragma unroll
        for (int w = 0; w < 4; w++) if (w < wid) wbase += swarp[w];
        int ex = wbase + incl - s;
        #pragma unroll
        for (int k = 0; k < 8; k++) {
            int j = tid * 8 + k;
            soff[j] = ex;
            g_offsets[j] = ex;
            ex += c[k];
        }
        if (tid == MEGA_T - 1) g_offsets[1024] = BATCH;
        __syncthreads();

        // pass 2: scatter (no atomics — rank precomputed)
        #pragma unroll
        for (int i = tid; i < BATCH / 4; i += MEGA_T) {
            int4 t = t4[i];
            int b = i * 4;
            g_rows[soff[t.x] + g_rank[b]]     = b;
            g_rows[soff[t.y] + g_rank[b + 1]] = b + 1;
            g_rows[soff[t.z] + g_rank[b + 2]] = b + 2;
            g_rows[soff[t.w] + g_rank[b + 3]] = b + 3;
        }

        __threadfence();
        __syncthreads();
        if (tid == 0)
            asm volatile("st.release.gpu.global.u32 [%0], %1;"
                         :: "l"(&g_flag), "r"(1) : "memory");

    } else if (bid < FIRST_FUSED) {
        // =================== CE role: warp-per-row, 4 rows per block ========
        const int rb   = bid - FIRST_CE;
        const int warp = tid >> 5;
        const int lane = tid & 31;
        const int row  = rb * 4 + warp;
        const float4* lrow4 =
            reinterpret_cast<const float4*>(logits + (size_t)row * NCLS);

        float4 v[8];
        #pragma unroll
        for (int k = 0; k < 7; k++) v[k] = lrow4[lane + k * 32];
        const bool has7 = lane < (250 - 7 * 32);   // 26 remaining float4
        v[7] = has7 ? lrow4[lane + 224]
                    : make_float4(-INFINITY, -INFINITY, -INFINITY, -INFINITY);

        float mx = -INFINITY;
        #pragma unroll
        for (int k = 0; k < 8; k++)
            mx = fmaxf(mx, fmaxf(fmaxf(v[k].x, v[k].y), fmaxf(v[k].z, v[k].w)));
        #pragma unroll
        for (int o = 16; o; o >>= 1)
            mx = fmaxf(mx, __shfl_xor_sync(0xffffffffu, mx, o));

        float sum = 0.f;
        #pragma unroll
        for (int k = 0; k < 7; k++)
            sum += __expf(v[k].x - mx) + __expf(v[k].y - mx) +
                   __expf(v[k].z - mx) + __expf(v[k].w - mx);
        if (has7)
            sum += __expf(v[7].x - mx) + __expf(v[7].y - mx) +
                   __expf(v[7].z - mx) + __expf(v[7].w - mx);
        #pragma unroll
        for (int o = 16; o; o >>= 1) sum += __shfl_xor_sync(0xffffffffu, sum, o);

        if (lane == 0) {
            float lse = mx + __logf(sum);
            float lt  = logits[(size_t)row * NCLS + target[row]];
            sred[warp] = lse - lt;
        }
        __syncthreads();
        if (tid == 0) {
            float t = sred[0] + sred[1] + sred[2] + sred[3];
            atomicAdd(&g_l1_slots[bid & (NSLOTS - 1)], (double)t);
        }

    } else {
        // =================== fused role ======================================
        // wait for prep (block 0 is wave-1 resident -> no deadlock)
        if (tid == 0) {
            unsigned f;
            do {
                asm volatile("ld.acquire.gpu.global.u32 %0, [%1];"
                             : "=r"(f) : "l"(&g_flag) : "memory");
            } while (f == 0);
        }
        __syncthreads();

        const int fb   = bid - FIRST_FUSED;
        const int c    = fb >> 2;
        const int col0 = ((fb & 3) * TILE_D) + tid * 4;
        const int col1 = col0 + (TILE_D / 2);

        const float4 y0 = *reinterpret_cast<const float4*>(
            dense_labels + (size_t)c * DDIM + col0);
        const float4 y1 = *reinterpret_cast<const float4*>(
            dense_labels + (size_t)c * DDIM + col1);

        float4 acc0 = make_float4(0.f, 0.f, 0.f, 0.f);
        float4 acc1 = make_float4(0.f, 0.f, 0.f, 0.f);
        float bce = 0.f;

        const int s = g_offsets[c];
        const int e = g_offsets[c + 1];

        int i = s;
        for (; i + 1 < e; i += 2) {
            const float* p0 = dense_out + (size_t)g_rows[i]     * DDIM;
            const float* p1 = dense_out + (size_t)g_rows[i + 1] * DDIM;
            const float4 a0 = *reinterpret_cast<const float4*>(p0 + col0);
            const float4 a1 = *reinterpret_cast<const float4*>(p0 + col1);
            const float4 b0 = *reinterpret_cast<const float4*>(p1 + col0);
            const float4 b1 = *reinterpret_cast<const float4*>(p1 + col1);
            acc4(a0, y0, acc0, bce);
            acc4(a1, y1, acc1, bce);
            acc4(b0, y0, acc0, bce);
            acc4(b1, y1, acc1, bce);
        }
        if (i < e) {
            const float* p0 = dense_out + (size_t)g_rows[i] * DDIM;
            const float4 a0 = *reinterpret_cast<const float4*>(p0 + col0);
            const float4 a1 = *reinterpret_cast<const float4*>(p0 + col1);
            acc4(a0, y0, acc0, bce);
            acc4(a1, y1, acc1, bce);
        }

        // scalar stores: out_sum is only 4B-aligned (d_out + 1 float)
        float* dst0 = out_sum + (size_t)c * DDIM + col0;
        dst0[0] = acc0.x; dst0[1] = acc0.y; dst0[2] = acc0.z; dst0[3] = acc0.w;
        float* dst1 = out_sum + (size_t)c * DDIM + col1;
        dst1[0] = acc1.x; dst1[1] = acc1.y; dst1[2] = acc1.z; dst1[3] = acc1.w;

        // block-reduce bce -> one spread double atomic
        #pragma unroll
        for (int o = 16; o; o >>= 1) bce += __shfl_xor_sync(0xffffffffu, bce, o);
        if ((tid & 31) == 0) sred[tid >> 5] = bce;
        __syncthreads();
        if (tid == 0) {
            float t = sred[0] + sred[1] + sred[2] + sred[3];
            atomicAdd(&g_l2_slots[bid & (NSLOTS - 1)], (double)t);
        }
    }
}

// ---------------------------------------------------------------------------
// finalize: one warp sums slot doubles; also resets g_flag for next replay
// ---------------------------------------------------------------------------
__global__ void finalize_kernel(float* __restrict__ out_loss) {
    const int lane = threadIdx.x;   // 32 threads
    double s1 = g_l1_slots[lane] + g_l1_slots[lane + 32];
    double s2 = g_l2_slots[lane] + g_l2_slots[lane + 32];
    #pragma unroll
    for (int o = 16; o; o >>= 1) {
        s1 += __shfl_xor_sync(0xffffffffu, s1, o);
        s2 += __shfl_xor_sync(0xffffffffu, s2, o);
    }
    if (lane == 0) {
        double loss1 = s1 / (double)BATCH;
        double loss2 = s2 / ((double)BATCH * (double)DDIM);
        out_loss[0] = (float)(0.5 * loss1 + 0.5 * loss2);
        g_flag = 0;   // reset for the next graph replay
    }
}

// ---------------------------------------------------------------------------
// Launch. Output layout (float32): [loss(1) | dense_output_sum(C*D) | total(C)]
// ---------------------------------------------------------------------------
extern "C" void kernel_launch(void* const* d_in, const int* in_sizes, int n_in,
                              void* d_out, int out_size) {
    const float* logits       = (const float*)d_in[0]; // [B, C]
    const float* dense_out    = (const float*)d_in[1]; // [B, D]
    const int*   target       = (const int*)  d_in[2]; // [B]
    const float* dense_labels = (const float*)d_in[3]; // [C, D]

    float* out       = (float*)d_out;
    float* out_loss  = out;
    float* out_sum   = out + 1;
    float* out_total = out + 1 + (size_t)NCLS * DDIM;

    mega_kernel<<<GRID, MEGA_T>>>(dense_out, dense_labels, logits, target,
                                  out_sum, out_total);

    finalize_kernel<<<1, 32>>>(out_loss);
}

// round 8
// speedup vs baseline: 1.4439x; 1.4439x over previous
#include <cuda_runtime.h>
#include <math.h>

// Problem constants (fixed by the reference)
#define BATCH 8192
#define NCLS  1000
#define DDIM  4096

#define TILE_D      1024
#define NT_D        (DDIM / TILE_D)       // 4 tiles over D
#define NF_BLOCKS   (NCLS * NT_D)         // 4000 fused blocks
#define CE_BLOCKS   (BATCH / 4)           // 2048 CE blocks (warp-per-row, 4/block)
#define FIRST_FUSED CE_BLOCKS
#define GRID_TOTAL  (CE_BLOCKS + NF_BLOCKS)
#define MEGA_T      128
#define NSLOTS      64

// ---------------------------------------------------------------------------
// Device scratch (no allocations allowed)
// ---------------------------------------------------------------------------
__device__ int    g_offsets[1025];     // exclusive class offsets (bins padded)
__device__ int    g_rows[BATCH];       // row ids grouped by class
__device__ int    g_rank[BATCH];       // per-row rank within its class
__device__ double g_l1_slots[NSLOTS];
__device__ double g_l2_slots[NSLOTS];
__device__ int    g_done = 0;          // arrival ticket (reset by last block)

// ---------------------------------------------------------------------------
// 1) prep: zero slots + histogram(rank) + warp-scan + scatter + totals
// ---------------------------------------------------------------------------
__global__ __launch_bounds__(1024)
void prep_kernel(const int* __restrict__ target, float* __restrict__ total_out) {
    __shared__ int scnt[1024];
    __shared__ int soff[1024];
    __shared__ int swarp[32];
    const int tid  = threadIdx.x;
    const int lane = tid & 31;
    const int wid  = tid >> 5;

    if (tid < NSLOTS) { g_l1_slots[tid] = 0.0; g_l2_slots[tid] = 0.0; }
    scnt[tid] = 0;
    __syncthreads();

    // histogram: atomic return value IS the row's rank within its class
    const int4* t4 = reinterpret_cast<const int4*>(target);
    #pragma unroll
    for (int i = tid; i < BATCH / 4; i += 1024) {
        int4 t = t4[i];
        int b = i * 4;
        g_rank[b]     = atomicAdd(&scnt[t.x], 1);
        g_rank[b + 1] = atomicAdd(&scnt[t.y], 1);
        g_rank[b + 2] = atomicAdd(&scnt[t.z], 1);
        g_rank[b + 3] = atomicAdd(&scnt[t.w], 1);
    }
    __syncthreads();

    const int v = scnt[tid];
    if (tid < NCLS) total_out[tid] = (float)v;

    // exclusive scan: warp inclusive scan + warp-base scan
    int incl = v;
    #pragma unroll
    for (int o = 1; o < 32; o <<= 1) {
        int n = __shfl_up_sync(0xffffffffu, incl, o);
        if (lane >= o) incl += n;
    }
    if (lane == 31) swarp[wid] = incl;
    __syncthreads();
    if (wid == 0) {
        int w = swarp[lane];
        int wi = w;
        #pragma unroll
        for (int o = 1; o < 32; o <<= 1) {
            int n = __shfl_up_sync(0xffffffffu, wi, o);
            if (lane >= o) wi += n;
        }
        swarp[lane] = wi - w;   // exclusive warp base
    }
    __syncthreads();
    const int ex = swarp[wid] + incl - v;
    soff[tid] = ex;
    g_offsets[tid] = ex;
    if (tid == 1023) g_offsets[1024] = BATCH;
    __syncthreads();

    // scatter (no atomics — ranks precomputed by this same thread)
    #pragma unroll
    for (int i = tid; i < BATCH / 4; i += 1024) {
        int4 t = t4[i];
        int b = i * 4;
        g_rows[soff[t.x] + g_rank[b]]     = b;
        g_rows[soff[t.y] + g_rank[b + 1]] = b + 1;
        g_rows[soff[t.z] + g_rank[b + 2]] = b + 2;
        g_rows[soff[t.w] + g_rank[b + 3]] = b + 3;
    }
}

// ---------------------------------------------------------------------------
// Element op: 2 MUFU (EX2, LG2). Reciprocal of u = 1+e, u in (1,2], via
// Newton with the seed RESCALED for (1,2]:  r0 = 24/17 - (8/17) u
// (classic 48/17 - 32/17 u' with u' = u/2, halved). Seed rel err <= 1/17;
// two iterations -> ~1e-5 rel err (tolerance 1e-3).
//   e = exp(-|x|); r = 1/(1+e); sig = x>=0 ? r : 1-r
//   bce += max(x,0) - x*y + log(1+e)
// ---------------------------------------------------------------------------
__device__ __forceinline__ void elem_op(float x, float y, float& acc, float& bce) {
    const float e = __expf(-fabsf(x));
    const float u = 1.f + e;
    float r = fmaf(-0.47058824f, u, 1.4117647f);  // seed valid on (1,2]
    r = r * fmaf(-u, r, 2.f);
    r = r * fmaf(-u, r, 2.f);
    acc += (x >= 0.f) ? r : (1.f - r);
    bce += fmaxf(x, 0.f) - x * y + __logf(u);
}

__device__ __forceinline__ void acc4(const float4 x4, const float4 y4,
                                     float4& acc, float& bce) {
    elem_op(x4.x, y4.x, acc.x, bce);
    elem_op(x4.y, y4.y, acc.y, bce);
    elem_op(x4.z, y4.z, acc.z, bce);
    elem_op(x4.w, y4.w, acc.w, bce);
}

// ---------------------------------------------------------------------------
// last-block loss reduction (shared by both roles)
// ---------------------------------------------------------------------------
__device__ __forceinline__ void arrive_and_maybe_finalize(int tid, float* out_loss) {
    __shared__ int s_last;
    if (tid == 0) {
        __threadfence();
        s_last = (atomicAdd(&g_done, 1) == GRID_TOTAL - 1);
    }
    __syncthreads();
    if (s_last && tid < 32) {
        __threadfence();
        double s1 = g_l1_slots[tid] + g_l1_slots[tid + 32];
        double s2 = g_l2_slots[tid] + g_l2_slots[tid + 32];
        #pragma unroll
        for (int o = 16; o; o >>= 1) {
            s1 += __shfl_xor_sync(0xffffffffu, s1, o);
            s2 += __shfl_xor_sync(0xffffffffu, s2, o);
        }
        if (tid == 0) {
            double loss1 = s1 / (double)BATCH;
            double loss2 = s2 / ((double)BATCH * (double)DDIM);
            out_loss[0] = (float)(0.5 * loss1 + 0.5 * loss2);
            g_done = 0;   // reset for the next graph replay
        }
    }
}

// ---------------------------------------------------------------------------
// 2) mega kernel: bid < CE_BLOCKS -> CE (warp-per-row, 4 rows/block)
//                 else            -> fused segment-sum+BCE tile
// ---------------------------------------------------------------------------
__global__ __launch_bounds__(MEGA_T)
void mega_kernel(const float* __restrict__ dense_out,
                 const float* __restrict__ dense_labels,
                 const float* __restrict__ logits,
                 const int*   __restrict__ target,
                 float* __restrict__ out_sum,
                 float* __restrict__ out_loss) {
    const int bid = blockIdx.x;
    const int tid = threadIdx.x;
    __shared__ float sred[MEGA_T / 32];

    if (bid < CE_BLOCKS) {
        // ----- CE role: warp-per-row, 4 rows per block -----
        const int warp = tid >> 5;
        const int lane = tid & 31;
        const int row  = bid * 4 + warp;
        const float4* lrow4 =
            reinterpret_cast<const float4*>(logits + (size_t)row * NCLS);

        float4 v[8];
        #pragma unroll
        for (int k = 0; k < 7; k++) v[k] = lrow4[lane + k * 32];
        const bool has7 = lane < (250 - 7 * 32);   // 26 remaining float4
        v[7] = has7 ? lrow4[lane + 224]
                    : make_float4(-INFINITY, -INFINITY, -INFINITY, -INFINITY);

        float mx = -INFINITY;
        #pragma unroll
        for (int k = 0; k < 8; k++)
            mx = fmaxf(mx, fmaxf(fmaxf(v[k].x, v[k].y), fmaxf(v[k].z, v[k].w)));
        #pragma unroll
        for (int o = 16; o; o >>= 1)
            mx = fmaxf(mx, __shfl_xor_sync(0xffffffffu, mx, o));

        float sum = 0.f;
        #pragma unroll
        for (int k = 0; k < 7; k++)
            sum += __expf(v[k].x - mx) + __expf(v[k].y - mx) +
                   __expf(v[k].z - mx) + __expf(v[k].w - mx);
        if (has7)
            sum += __expf(v[7].x - mx) + __expf(v[7].y - mx) +
                   __expf(v[7].z - mx) + __expf(v[7].w - mx);
        #pragma unroll
        for (int o = 16; o; o >>= 1) sum += __shfl_xor_sync(0xffffffffu, sum, o);

        if (lane == 0) {
            float lse = mx + __logf(sum);
            float lt  = logits[(size_t)row * NCLS + target[row]];
            sred[warp] = lse - lt;
        }
        __syncthreads();
        if (tid == 0) {
            float t = sred[0] + sred[1] + sred[2] + sred[3];
            atomicAdd(&g_l1_slots[bid & (NSLOTS - 1)], (double)t);
        }

    } else {
        // ----- fused role: class c, D-tile of 1024 cols, 2 float4/thread ----
        const int fb   = bid - FIRST_FUSED;
        const int c    = fb >> 2;
        const int col0 = ((fb & 3) * TILE_D) + tid * 4;
        const int col1 = col0 + (TILE_D / 2);

        const float4 y0 = *reinterpret_cast<const float4*>(
            dense_labels + (size_t)c * DDIM + col0);
        const float4 y1 = *reinterpret_cast<const float4*>(
            dense_labels + (size_t)c * DDIM + col1);

        float4 acc0 = make_float4(0.f, 0.f, 0.f, 0.f);
        float4 acc1 = make_float4(0.f, 0.f, 0.f, 0.f);
        float bce = 0.f;

        const int s = g_offsets[c];
        const int e = g_offsets[c + 1];

        int i = s;
        for (; i + 1 < e; i += 2) {
            const float* p0 = dense_out + (size_t)g_rows[i]     * DDIM;
            const float* p1 = dense_out + (size_t)g_rows[i + 1] * DDIM;
            const float4 a0 = *reinterpret_cast<const float4*>(p0 + col0);
            const float4 a1 = *reinterpret_cast<const float4*>(p0 + col1);
            const float4 b0 = *reinterpret_cast<const float4*>(p1 + col0);
            const float4 b1 = *reinterpret_cast<const float4*>(p1 + col1);
            acc4(a0, y0, acc0, bce);
            acc4(a1, y1, acc1, bce);
            acc4(b0, y0, acc0, bce);
            acc4(b1, y1, acc1, bce);
        }
        if (i < e) {
            const float* p0 = dense_out + (size_t)g_rows[i] * DDIM;
            const float4 a0 = *reinterpret_cast<const float4*>(p0 + col0);
            const float4 a1 = *reinterpret_cast<const float4*>(p0 + col1);
            acc4(a0, y0, acc0, bce);
            acc4(a1, y1, acc1, bce);
        }

        // scalar stores: out_sum is only 4B-aligned (d_out + 1 float)
        float* dst0 = out_sum + (size_t)c * DDIM + col0;
        dst0[0] = acc0.x; dst0[1] = acc0.y; dst0[2] = acc0.z; dst0[3] = acc0.w;
        float* dst1 = out_sum + (size_t)c * DDIM + col1;
        dst1[0] = acc1.x; dst1[1] = acc1.y; dst1[2] = acc1.z; dst1[3] = acc1.w;

        // block-reduce bce -> one spread double atomic
        #pragma unroll
        for (int o = 16; o; o >>= 1) bce += __shfl_xor_sync(0xffffffffu, bce, o);
        if ((tid & 31) == 0) sred[tid >> 5] = bce;
        __syncthreads();
        if (tid == 0) {
            float t = sred[0] + sred[1] + sred[2] + sred[3];
            atomicAdd(&g_l2_slots[bid & (NSLOTS - 1)], (double)t);
        }
    }

    arrive_and_maybe_finalize(tid, out_loss);
}

// ---------------------------------------------------------------------------
// Launch. Output layout (float32): [loss(1) | dense_output_sum(C*D) | total(C)]
// ---------------------------------------------------------------------------
extern "C" void kernel_launch(void* const* d_in, const int* in_sizes, int n_in,
                              void* d_out, int out_size) {
    const float* logits       = (const float*)d_in[0]; // [B, C]
    const float* dense_out    = (const float*)d_in[1]; // [B, D]
    const int*   target       = (const int*)  d_in[2]; // [B]
    const float* dense_labels = (const float*)d_in[3]; // [C, D]

    float* out       = (float*)d_out;
    float* out_loss  = out;
    float* out_sum   = out + 1;
    float* out_total = out + 1 + (size_t)NCLS * DDIM;

    prep_kernel<<<1, 1024>>>(target, out_total);

    mega_kernel<<<GRID_TOTAL, MEGA_T>>>(dense_out, dense_labels, logits, target,
                                        out_sum, out_loss);
}